// round 6
// baseline (speedup 1.0000x reference)
#include <cuda_runtime.h>
#include <cstdint>

// Problem constants (fixed shapes from reference)
#define BATCH 32
#define HW    16384       // 128*128
#define NCLS  80
#define NPB   (HW * NCLS) // 1310720 scores per batch
#define N4    (NPB / 4)   // 327680 float4 per batch
#define KTOP  100
#define BINS  2048        // top-11 bits of monotonic key
#define CAP   4096        // candidate buffer per batch

#define SAMPLE_STRIDE 64          // in float4 units -> 1/64 of elements sampled
#define NSAMP4 (N4 / SAMPLE_STRIDE)  // 5120 float4 = 20480 samples per batch
#define STARGET 4u                // sampled suffix target (~256 expected true)
#define SMARGIN 2                 // extra bins below the sampled cut

// __device__ scratch (no allocation allowed)
__device__ unsigned int g_hist[BATCH][BINS];   // sampled histogram
__device__ unsigned int g_hist2[BATCH][BINS];  // exact histogram (fallback)
__device__ int          g_cnt[BATCH];
__device__ float        g_thresh[BATCH];       // float-domain cutoff
__device__ int          g_flag;                // fallback trigger
__device__ uint2        g_cand[BATCH][CAP];    // (float bits, linear index)

// Order-preserving float->uint mapping (descending float == descending key)
__device__ __forceinline__ unsigned int f2key(float f) {
    unsigned int u = __float_as_uint(f);
    return (u & 0x80000000u) ? ~u : (u | 0x80000000u);
}
__device__ __forceinline__ unsigned int u2key(unsigned int u) {
    return (u & 0x80000000u) ? ~u : (u | 0x80000000u);
}
__device__ __forceinline__ float key2f(unsigned int k) {
    unsigned int u = (k & 0x80000000u) ? (k ^ 0x80000000u) : ~k;
    return __uint_as_float(u);
}

// ---------------------------------------------------------------------------
// Pass 0: zero scratch
__global__ void zero_kernel() {
    const int total = BATCH * BINS;
    for (int i = blockIdx.x * blockDim.x + threadIdx.x; i < total;
         i += gridDim.x * blockDim.x) {
        ((unsigned int*)g_hist)[i]  = 0;
        ((unsigned int*)g_hist2)[i] = 0;
    }
    if (blockIdx.x == 0 && threadIdx.x < BATCH) g_cnt[threadIdx.x] = 0;
    if (blockIdx.x == 0 && threadIdx.x == 0)    g_flag = 0;
}

// ---------------------------------------------------------------------------
// Pass 1: sampled histogram — one block per batch, 1/64 of elements
__global__ void sample_kernel(const float* __restrict__ cls) {
    __shared__ unsigned int sh[BINS];
    const int b = blockIdx.x;
    for (int i = threadIdx.x; i < BINS; i += blockDim.x) sh[i] = 0;
    __syncthreads();

    const float4* p = (const float4*)(cls + (size_t)b * NPB);
    for (int k = threadIdx.x; k < NSAMP4; k += blockDim.x) {
        float4 v = p[(size_t)k * SAMPLE_STRIDE];
        atomicAdd(&sh[f2key(v.x) >> 21], 1u);
        atomicAdd(&sh[f2key(v.y) >> 21], 1u);
        atomicAdd(&sh[f2key(v.z) >> 21], 1u);
        atomicAdd(&sh[f2key(v.w) >> 21], 1u);
    }
    __syncthreads();
    for (int i = threadIdx.x; i < BINS; i += blockDim.x) g_hist[b][i] = sh[i];
}

// ---------------------------------------------------------------------------
// Cutoff finder: suffix-scan of a histogram from the top. mode 0 = sampled
// (target STARGET, margin SMARGIN, from g_hist). mode 1 = exact fallback
// (target KTOP, margin 0, from g_hist2, predicated on g_flag).
#define CUT_THREADS 256
#define CHUNK (BINS / CUT_THREADS)   // 8 bins per thread
__global__ void cut_kernel(int mode) {
    if (mode == 1 && g_flag == 0) return;
    __shared__ unsigned int sb[BINS];
    __shared__ unsigned int csum[CUT_THREADS];
    const int b = blockIdx.x;
    const int t = threadIdx.x;
    const unsigned int target = (mode == 0) ? STARGET : (unsigned int)KTOP;
    const int margin = (mode == 0) ? SMARGIN : 0;
    const unsigned int* hist = (mode == 0) ? g_hist[b] : g_hist2[b];

    #pragma unroll
    for (int i = 0; i < CHUNK; i++)
        sb[t + i * CUT_THREADS] = hist[t + i * CUT_THREADS];
    __syncthreads();

    unsigned int s = 0;
    #pragma unroll
    for (int i = 0; i < CHUNK; i++) s += sb[t * CHUNK + i];
    csum[t] = s;
    __syncthreads();

    if (t == 0) {
        unsigned int acc = 0;
        int cut = 0;
        for (int c = CUT_THREADS - 1; c >= 0; c--) {
            unsigned int ns = acc + csum[c];
            if (ns >= target) {
                for (int i = CHUNK - 1; i >= 0; i--) {
                    acc += sb[c * CHUNK + i];
                    if (acc >= target) { cut = c * CHUNK + i; break; }
                }
                break;
            }
            acc = ns;
        }
        cut -= margin;
        if (cut < 0) cut = 0;
        g_thresh[b] = key2f((unsigned int)cut << 21);
    }
}

// ---------------------------------------------------------------------------
// Collect: float-domain threshold compare (1 FSETP/elem), rare atomic append.
// mode 1 = fallback re-collect (predicated on g_flag).
__global__ void collect_kernel(const float* __restrict__ cls, int mode) {
    if (mode == 1 && g_flag == 0) return;
    const int b = blockIdx.y;
    const float Tf = g_thresh[b];
    const float4* p = (const float4*)(cls + (size_t)b * NPB);
    const int stride = gridDim.x * blockDim.x;

    for (int i = blockIdx.x * blockDim.x + threadIdx.x; i < N4; i += stride) {
        float4 v = p[i];
        #pragma unroll
        for (int j = 0; j < 4; j++) {
            float val = (j == 0) ? v.x : (j == 1) ? v.y : (j == 2) ? v.z : v.w;
            if (val >= Tf) {
                int pos = atomicAdd(&g_cnt[b], 1);
                if (pos < CAP)
                    g_cand[b][pos] =
                        make_uint2(__float_as_uint(val), (unsigned int)(4 * i + j));
            }
        }
    }
}

// ---------------------------------------------------------------------------
// Verify candidate counts; trigger exact fallback if the sampled cut failed.
__global__ void check_kernel() {
    const int t = threadIdx.x;  // 32 threads
    int c = g_cnt[t];
    int bad = (c < KTOP) || (c > CAP);
    unsigned int m = __ballot_sync(0xffffffffu, bad);
    if (m) {
        if (t == 0) g_flag = 1;
        g_cnt[t] = 0;  // restart collection for the exact pass
    }
}

// ---------------------------------------------------------------------------
// Fallback exact histogram (only runs if the sampled path failed)
__global__ void fb_hist_kernel(const float* __restrict__ cls) {
    if (g_flag == 0) return;
    __shared__ unsigned int sh[BINS];
    const int b = blockIdx.y;
    for (int i = threadIdx.x; i < BINS; i += blockDim.x) sh[i] = 0;
    __syncthreads();

    const float4* p = (const float4*)(cls + (size_t)b * NPB);
    const int stride = gridDim.x * blockDim.x;
    const int lane = threadIdx.x & 31;

    for (int i = blockIdx.x * blockDim.x + threadIdx.x; i < N4; i += stride) {
        float4 v = p[i];
        unsigned int ks[4] = { f2key(v.x) >> 21, f2key(v.y) >> 21,
                               f2key(v.z) >> 21, f2key(v.w) >> 21 };
        #pragma unroll
        for (int j = 0; j < 4; j++) {
            unsigned int mask = __match_any_sync(0xffffffffu, ks[j]);
            int leader = __ffs(mask) - 1;
            if (lane == leader) atomicAdd(&sh[ks[j]], (unsigned int)__popc(mask));
        }
    }
    __syncthreads();
    for (int i = threadIdx.x; i < BINS; i += blockDim.x)
        if (sh[i]) atomicAdd(&g_hist2[b][i], sh[i]);
}

// ---------------------------------------------------------------------------
// Select: exact rank among candidates (key desc, index asc = jax top_k
// semantics), gather boxes, write [B, K, 6] output.
__global__ void select_kernel(const float* __restrict__ loc,
                              float* __restrict__ out) {
    __shared__ uint2 cand[CAP];
    const int b = blockIdx.x;
    const int n = min(g_cnt[b], CAP);
    for (int i = threadIdx.x; i < n; i += blockDim.x) cand[i] = g_cand[b][i];
    __syncthreads();

    for (int i = threadIdx.x; i < n; i += blockDim.x) {
        const unsigned int ki = u2key(cand[i].x);
        const unsigned int xi = cand[i].y;
        int rank = 0;
        for (int j = 0; j < n; j++) {
            unsigned int kj = u2key(cand[j].x);
            unsigned int xj = cand[j].y;
            rank += (kj > ki) || (kj == ki && xj < xi);
        }
        if (rank < KTOP) {
            unsigned int cls_id = xi % NCLS;
            unsigned int sp = xi / NCLS;
            float4 box = ((const float4*)(loc + (size_t)b * HW * 4))[sp];
            float* o = out + ((size_t)b * KTOP + rank) * 6;
            o[0] = box.x; o[1] = box.y; o[2] = box.z; o[3] = box.w;
            o[4] = key2f(ki);
            o[5] = (float)cls_id;
        }
    }
}

// ---------------------------------------------------------------------------
extern "C" void kernel_launch(void* const* d_in, const int* in_sizes, int n_in,
                              void* d_out, int out_size) {
    const float* cls = (const float*)d_in[0];
    const float* loc = (const float*)d_in[1];
    if (n_in >= 2 && in_sizes[0] < in_sizes[1]) {
        cls = (const float*)d_in[1];
        loc = (const float*)d_in[0];
    }
    float* out = (float*)d_out;

    zero_kernel<<<256, 256>>>();
    sample_kernel<<<BATCH, 1024>>>(cls);
    cut_kernel<<<BATCH, CUT_THREADS>>>(0);
    collect_kernel<<<dim3(128, BATCH), 256>>>(cls, 0);
    check_kernel<<<1, 32>>>();
    // Predicated exact fallback (early-exits when the sampled path succeeded)
    fb_hist_kernel<<<dim3(128, BATCH), 256>>>(cls);
    cut_kernel<<<BATCH, CUT_THREADS>>>(1);
    collect_kernel<<<dim3(128, BATCH), 256>>>(cls, 1);
    select_kernel<<<BATCH, 512>>>(loc, out);
}

// round 11
// speedup vs baseline: 1.8650x; 1.8650x over previous
#include <cuda_runtime.h>
#include <cstdint>

#define BATCH 32
#define HW    16384
#define NCLS  80
#define NPB   (HW * NCLS)    // 1310720
#define N4    (NPB / 4)      // 327680
#define KTOP  100
#define BINS  2048
#define CAP   4096

#define SAMPLE_STRIDE 64             // float4 stride -> 1/64 of elements
#define NSAMP4 (N4 / SAMPLE_STRIDE)  // 5120 float4 = 20480 samples/batch
#define RANK   16                    // sampled order statistic target

// scratch (no allocation allowed)
__device__ unsigned int g_hist2[BATCH][BINS];  // exact hist (fallback only)
__device__ int          g_cnt[BATCH];
__device__ float        g_thresh[BATCH];
__device__ int          g_flag;
__device__ uint2        g_cand[BATCH][CAP];    // (float bits, linear index)

__device__ __forceinline__ unsigned int f2key(float f) {
    unsigned int u = __float_as_uint(f);
    return (u & 0x80000000u) ? ~u : (u | 0x80000000u);
}
__device__ __forceinline__ unsigned int u2key(unsigned int u) {
    return (u & 0x80000000u) ? ~u : (u | 0x80000000u);
}
__device__ __forceinline__ float key2f(unsigned int k) {
    unsigned int u = (k & 0x80000000u) ? (k ^ 0x80000000u) : ~k;
    return __uint_as_float(u);
}

// ---------------------------------------------------------------------------
__global__ void zero_kernel() {
    const int total = BATCH * BINS;
    int i = blockIdx.x * blockDim.x + threadIdx.x;
    if (i < total) ((unsigned int*)g_hist2)[i] = 0;
    if (i < BATCH) g_cnt[i] = 0;
    if (i == 0)    g_flag = 0;
}

// ---------------------------------------------------------------------------
// Sampled two-level quantile: one block per batch.
// Pass A: coarse hist of key>>21 over samples -> coarse bin of RANK-th sample.
// Pass B: fine hist of (key>>10)&0x7FF within that bin -> 22-bit threshold.
__global__ void sample_cut_kernel(const float* __restrict__ cls) {
    __shared__ unsigned int sb[BINS];
    __shared__ unsigned int csum[256];
    __shared__ int s_cb;
    __shared__ unsigned int s_above;
    const int b = blockIdx.x;
    const int t = threadIdx.x;          // 1024 threads

    for (int i = t; i < BINS; i += blockDim.x) sb[i] = 0;
    __syncthreads();

    const float4* p = (const float4*)(cls + (size_t)b * NPB);
    // Pass A: coarse histogram
    for (int k = t; k < NSAMP4; k += blockDim.x) {
        float4 v = p[(size_t)k * SAMPLE_STRIDE];
        atomicAdd(&sb[f2key(v.x) >> 21], 1u);
        atomicAdd(&sb[f2key(v.y) >> 21], 1u);
        atomicAdd(&sb[f2key(v.z) >> 21], 1u);
        atomicAdd(&sb[f2key(v.w) >> 21], 1u);
    }
    __syncthreads();

    // chunked suffix scan: 8 bins/chunk over first 256 threads
    if (t < 256) {
        unsigned int s = 0;
        #pragma unroll
        for (int i = 0; i < 8; i++) s += sb[t * 8 + i];
        csum[t] = s;
    }
    __syncthreads();
    if (t == 0) {
        unsigned int acc = 0;
        int cb = 0;
        for (int c = 255; c >= 0; c--) {
            unsigned int ns = acc + csum[c];
            if (ns >= RANK) {
                for (int i = 7; i >= 0; i--) {
                    unsigned int na = acc + sb[c * 8 + i];
                    if (na >= RANK) { cb = c * 8 + i; break; }
                    acc = na;
                }
                break;
            }
            acc = ns;
        }
        s_cb = cb;
        s_above = acc;   // count of samples strictly above bin cb
    }
    __syncthreads();
    const unsigned int cb = (unsigned int)s_cb;
    const unsigned int above = s_above;

    // Pass B: fine histogram within coarse bin cb
    for (int i = t; i < BINS; i += blockDim.x) sb[i] = 0;
    __syncthreads();
    for (int k = t; k < NSAMP4; k += blockDim.x) {
        float4 v = p[(size_t)k * SAMPLE_STRIDE];
        #pragma unroll
        for (int j = 0; j < 4; j++) {
            float f = (j == 0) ? v.x : (j == 1) ? v.y : (j == 2) ? v.z : v.w;
            unsigned int key = f2key(f);
            if ((key >> 21) == cb) atomicAdd(&sb[(key >> 10) & 0x7FFu], 1u);
        }
    }
    __syncthreads();
    if (t < 256) {
        unsigned int s = 0;
        #pragma unroll
        for (int i = 0; i < 8; i++) s += sb[t * 8 + i];
        csum[t] = s;
    }
    __syncthreads();
    if (t == 0) {
        unsigned int acc = above;
        unsigned int fb = 0;
        for (int c = 255; c >= 0; c--) {
            unsigned int ns = acc + csum[c];
            if (ns >= RANK) {
                for (int i = 7; i >= 0; i--) {
                    unsigned int na = acc + sb[c * 8 + i];
                    if (na >= RANK) { fb = (unsigned int)(c * 8 + i); break; }
                    acc = na;
                }
                break;
            }
            acc = ns;
        }
        unsigned int T = (cb << 21) | (fb << 10);
        g_thresh[b] = key2f(T);
    }
}

// ---------------------------------------------------------------------------
// Collect: one float-compare per element, rare atomic append.
__global__ void collect_kernel(const float* __restrict__ cls, int mode) {
    if (mode == 1 && g_flag == 0) return;
    const int b = blockIdx.y;
    const float Tf = g_thresh[b];
    const float4* p = (const float4*)(cls + (size_t)b * NPB);
    const int stride = gridDim.x * blockDim.x;

    for (int i = blockIdx.x * blockDim.x + threadIdx.x; i < N4; i += stride) {
        float4 v = __ldcs(&p[i]);
        #pragma unroll
        for (int j = 0; j < 4; j++) {
            float val = (j == 0) ? v.x : (j == 1) ? v.y : (j == 2) ? v.z : v.w;
            if (val >= Tf) {
                int pos = atomicAdd(&g_cnt[b], 1);
                if (pos < CAP)
                    g_cand[b][pos] =
                        make_uint2(__float_as_uint(val), (unsigned int)(4 * i + j));
            }
        }
    }
}

// ---------------------------------------------------------------------------
__global__ void check_kernel() {
    const int t = threadIdx.x;  // 32 threads
    int c = g_cnt[t];
    int bad = (c < KTOP) || (c > CAP);
    unsigned int m = __ballot_sync(0xffffffffu, bad);
    if (m) {
        if (t == 0) g_flag = 1;
        g_cnt[t] = 0;
    }
}

// ---------------------------------------------------------------------------
// Fallback exact histogram (runs only if sampled path failed)
__global__ void fb_hist_kernel(const float* __restrict__ cls) {
    if (g_flag == 0) return;
    __shared__ unsigned int sh[BINS];
    const int b = blockIdx.y;
    for (int i = threadIdx.x; i < BINS; i += blockDim.x) sh[i] = 0;
    __syncthreads();

    const float4* p = (const float4*)(cls + (size_t)b * NPB);
    const int stride = gridDim.x * blockDim.x;
    const int lane = threadIdx.x & 31;

    for (int i = blockIdx.x * blockDim.x + threadIdx.x; i < N4; i += stride) {
        float4 v = p[i];
        unsigned int ks[4] = { f2key(v.x) >> 21, f2key(v.y) >> 21,
                               f2key(v.z) >> 21, f2key(v.w) >> 21 };
        #pragma unroll
        for (int j = 0; j < 4; j++) {
            unsigned int mask = __match_any_sync(0xffffffffu, ks[j]);
            int leader = __ffs(mask) - 1;
            if (lane == leader) atomicAdd(&sh[ks[j]], (unsigned int)__popc(mask));
        }
    }
    __syncthreads();
    for (int i = threadIdx.x; i < BINS; i += blockDim.x)
        if (sh[i]) atomicAdd(&g_hist2[b][i], sh[i]);
}

// Fallback cutoff from the exact histogram (suffix >= KTOP, no margin)
__global__ void fb_cut_kernel() {
    if (g_flag == 0) return;
    __shared__ unsigned int sb[BINS];
    __shared__ unsigned int csum[256];
    const int b = blockIdx.x;
    const int t = threadIdx.x;   // 256 threads

    #pragma unroll
    for (int i = 0; i < 8; i++) sb[t + i * 256] = g_hist2[b][t + i * 256];
    __syncthreads();
    unsigned int s = 0;
    #pragma unroll
    for (int i = 0; i < 8; i++) s += sb[t * 8 + i];
    csum[t] = s;
    __syncthreads();
    if (t == 0) {
        unsigned int acc = 0;
        int cut = 0;
        for (int c = 255; c >= 0; c--) {
            unsigned int ns = acc + csum[c];
            if (ns >= KTOP) {
                for (int i = 7; i >= 0; i--) {
                    acc += sb[c * 8 + i];
                    if (acc >= KTOP) { cut = c * 8 + i; break; }
                }
                break;
            }
            acc = ns;
        }
        g_thresh[b] = key2f((unsigned int)cut << 21);
    }
}

// ---------------------------------------------------------------------------
// Select: exact rank (key desc, index asc = jax top_k), gather boxes.
__global__ void select_kernel(const float* __restrict__ loc,
                              float* __restrict__ out) {
    __shared__ uint2 cand[CAP];
    const int b = blockIdx.x;
    const int n = min(g_cnt[b], CAP);
    for (int i = threadIdx.x; i < n; i += blockDim.x) cand[i] = g_cand[b][i];
    __syncthreads();

    for (int i = threadIdx.x; i < n; i += blockDim.x) {
        const unsigned int ki = u2key(cand[i].x);
        const unsigned int xi = cand[i].y;
        int rank = 0;
        for (int j = 0; j < n; j++) {
            unsigned int kj = u2key(cand[j].x);
            unsigned int xj = cand[j].y;
            rank += (kj > ki) || (kj == ki && xj < xi);
        }
        if (rank < KTOP) {
            unsigned int cls_id = xi % NCLS;
            unsigned int sp = xi / NCLS;
            float4 box = ((const float4*)(loc + (size_t)b * HW * 4))[sp];
            float* o = out + ((size_t)b * KTOP + rank) * 6;
            o[0] = box.x; o[1] = box.y; o[2] = box.z; o[3] = box.w;
            o[4] = key2f(ki);
            o[5] = (float)cls_id;
        }
    }
}

// ---------------------------------------------------------------------------
extern "C" void kernel_launch(void* const* d_in, const int* in_sizes, int n_in,
                              void* d_out, int out_size) {
    const float* cls = (const float*)d_in[0];
    const float* loc = (const float*)d_in[1];
    if (n_in >= 2 && in_sizes[0] < in_sizes[1]) {
        cls = (const float*)d_in[1];
        loc = (const float*)d_in[0];
    }
    float* out = (float*)d_out;

    zero_kernel<<<256, 256>>>();
    sample_cut_kernel<<<BATCH, 1024>>>(cls);
    collect_kernel<<<dim3(128, BATCH), 256>>>(cls, 0);
    check_kernel<<<1, 32>>>();
    // predicated exact fallback (no-ops when sampled path succeeded)
    fb_hist_kernel<<<dim3(128, BATCH), 256>>>(cls);
    fb_cut_kernel<<<BATCH, 256>>>();
    collect_kernel<<<dim3(128, BATCH), 256>>>(cls, 1);
    select_kernel<<<BATCH, 512>>>(loc, out);
}

// round 12
// speedup vs baseline: 2.0640x; 1.1067x over previous
#include <cuda_runtime.h>
#include <cstdint>

#define BATCH 32
#define HW    16384
#define NCLS  80
#define NPB   (HW * NCLS)    // 1310720
#define N4    (NPB / 4)      // 327680
#define KTOP  100
#define BINS  2048
#define CAP   4096
#define STAGE 512            // per-block staging for collect

#define SAMPLE_STRIDE 64             // float4 stride -> 1/64 of elements
#define NSAMP4 (N4 / SAMPLE_STRIDE)  // 5120 float4 = 20480 samples/batch
#define RANK   16                    // threshold = 16th-largest sample
#define SBUF   1024                  // candidate-sample buffer

// device scratch (no allocation allowed)
__device__ unsigned int g_hist2[BATCH][BINS];  // exact hist (fallback only)
__device__ int          g_cnt[BATCH];
__device__ float        g_thresh[BATCH];
__device__ int          g_flag;
__device__ uint2        g_cand[BATCH][CAP];    // (float bits, linear index)

__device__ __forceinline__ unsigned int f2key(float f) {
    unsigned int u = __float_as_uint(f);
    return (u & 0x80000000u) ? ~u : (u | 0x80000000u);
}
__device__ __forceinline__ unsigned int u2key(unsigned int u) {
    return (u & 0x80000000u) ? ~u : (u | 0x80000000u);
}
__device__ __forceinline__ float key2f(unsigned int k) {
    unsigned int u = (k & 0x80000000u) ? (k ^ 0x80000000u) : ~k;
    return __uint_as_float(u);
}

// ---------------------------------------------------------------------------
__global__ void init_kernel() {
    int t = threadIdx.x;
    if (t < BATCH) g_cnt[t] = 0;
    if (t == 0)    g_flag = 0;
}

// ---------------------------------------------------------------------------
// Per-batch sampled threshold. One block of 1024 threads per batch.
// Pass A: coarse histogram (key>>21) of 20480 strided samples.
//         Suffix-scan locates coarse bin cb holding the RANK-th sample.
// Pass B: gather sample VALUES in bins >= cb (~40 of them), exact rank-select
//         the RANK-th largest -> threshold is an exact sample value.
__global__ void sample_cut_kernel(const float* __restrict__ cls) {
    __shared__ unsigned int sb[BINS];
    __shared__ unsigned int csum[256];
    __shared__ float sbuf[SBUF];
    __shared__ int   s_n;
    __shared__ int   s_cb;
    __shared__ float s_thresh;
    const int b = blockIdx.x;
    const int t = threadIdx.x;

    for (int i = t; i < BINS; i += blockDim.x) sb[i] = 0;
    if (t == 0) { s_n = 0; s_thresh = 0.f; }
    __syncthreads();

    const float4* p = (const float4*)(cls + (size_t)b * NPB);
    for (int k = t; k < NSAMP4; k += blockDim.x) {
        float4 v = p[(size_t)k * SAMPLE_STRIDE];
        atomicAdd(&sb[f2key(v.x) >> 21], 1u);
        atomicAdd(&sb[f2key(v.y) >> 21], 1u);
        atomicAdd(&sb[f2key(v.z) >> 21], 1u);
        atomicAdd(&sb[f2key(v.w) >> 21], 1u);
    }
    __syncthreads();

    if (t < 256) {
        unsigned int s = 0;
        #pragma unroll
        for (int i = 0; i < 8; i++) s += sb[t * 8 + i];
        csum[t] = s;
    }
    __syncthreads();
    if (t == 0) {
        unsigned int acc = 0;
        int cb = 0;
        for (int c = 255; c >= 0; c--) {
            if (acc + csum[c] >= RANK) {
                for (int i = 7; i >= 0; i--) {
                    if (acc + sb[c * 8 + i] >= RANK) { cb = c * 8 + i; goto done; }
                    acc += sb[c * 8 + i];
                }
            } else {
                acc += csum[c];
            }
        }
    done:
        s_cb = cb;
    }
    __syncthreads();
    const unsigned int cb = (unsigned int)s_cb;

    // Pass B: gather sample values in bins >= cb
    for (int k = t; k < NSAMP4; k += blockDim.x) {
        float4 v = p[(size_t)k * SAMPLE_STRIDE];
        #pragma unroll
        for (int j = 0; j < 4; j++) {
            float f = (j == 0) ? v.x : (j == 1) ? v.y : (j == 2) ? v.z : v.w;
            if ((f2key(f) >> 21) >= cb) {
                int pos = atomicAdd(&s_n, 1);
                if (pos < SBUF) sbuf[pos] = f;
            }
        }
    }
    __syncthreads();
    const int m = min(s_n, SBUF);   // m >= RANK by construction

    // exact rank select: RANK-th largest value (stable tie-break by slot)
    for (int i = t; i < m; i += blockDim.x) {
        float vi = sbuf[i];
        int r = 0;
        for (int j = 0; j < m; j++) {
            float vj = sbuf[j];
            r += (vj > vi) || (vj == vi && j < i);
        }
        if (r == RANK - 1) s_thresh = vi;
    }
    __syncthreads();
    if (t == 0) g_thresh[b] = s_thresh;
}

// ---------------------------------------------------------------------------
// Collect: streaming compare + warp-ballot -> shared staging -> ONE global
// atomic per block. Immune to threshold failure (no global atomic storm).
__global__ void collect_kernel(const float* __restrict__ cls, int mode) {
    if (mode == 1 && g_flag == 0) return;
    __shared__ uint2 stage[STAGE];
    __shared__ int s_n, s_base;
    const int b = blockIdx.y;
    const float Tf = g_thresh[b];
    if (threadIdx.x == 0) s_n = 0;
    __syncthreads();

    const float4* p = (const float4*)(cls + (size_t)b * NPB);
    const int stride = gridDim.x * blockDim.x;
    const int lane = threadIdx.x & 31;

    for (int i = blockIdx.x * blockDim.x + threadIdx.x; i < N4; i += stride) {
        float4 v = __ldcs(&p[i]);
        #pragma unroll
        for (int j = 0; j < 4; j++) {
            float val = (j == 0) ? v.x : (j == 1) ? v.y : (j == 2) ? v.z : v.w;
            bool hit = (val >= Tf);
            unsigned int mask = __ballot_sync(0xffffffffu, hit);
            if (mask) {
                int ld = __ffs(mask) - 1;
                int base = 0;
                if (lane == ld) base = atomicAdd(&s_n, __popc(mask));
                base = __shfl_sync(0xffffffffu, base, ld);
                if (hit) {
                    int pos = base + __popc(mask & ((1u << lane) - 1u));
                    if (pos < STAGE)
                        stage[pos] = make_uint2(__float_as_uint(val),
                                                (unsigned int)(4 * i + j));
                }
            }
        }
    }
    __syncthreads();
    const int n = s_n;
    if (threadIdx.x == 0) s_base = (n > 0) ? atomicAdd(&g_cnt[b], n) : 0;
    __syncthreads();
    const int base = s_base;
    const int nst = min(n, STAGE);
    for (int i = threadIdx.x; i < nst; i += blockDim.x) {
        int gpos = base + i;
        if (gpos < CAP) g_cand[b][gpos] = stage[i];
    }
}

// ---------------------------------------------------------------------------
// Check counts; if any batch out of [KTOP, CAP], arm fallback and reset state.
__global__ void check_kernel() {
    __shared__ int s_bad;
    const int t = threadIdx.x;   // 1024 threads
    if (t == 0) s_bad = 0;
    __syncthreads();
    if (t < BATCH) {
        int c = g_cnt[t];
        if (c < KTOP || c > CAP) atomicExch(&s_bad, 1);
    }
    __syncthreads();
    if (s_bad) {
        if (t == 0) g_flag = 1;
        if (t < BATCH) g_cnt[t] = 0;
        for (int i = t; i < BATCH * BINS; i += blockDim.x)
            ((unsigned int*)g_hist2)[i] = 0;
    }
}

// ---------------------------------------------------------------------------
// Fallback exact histogram (runs only if sampled path failed)
__global__ void fb_hist_kernel(const float* __restrict__ cls) {
    if (g_flag == 0) return;
    __shared__ unsigned int sh[BINS];
    const int b = blockIdx.y;
    for (int i = threadIdx.x; i < BINS; i += blockDim.x) sh[i] = 0;
    __syncthreads();

    const float4* p = (const float4*)(cls + (size_t)b * NPB);
    const int stride = gridDim.x * blockDim.x;
    const int lane = threadIdx.x & 31;

    for (int i = blockIdx.x * blockDim.x + threadIdx.x; i < N4; i += stride) {
        float4 v = p[i];
        unsigned int ks[4] = { f2key(v.x) >> 21, f2key(v.y) >> 21,
                               f2key(v.z) >> 21, f2key(v.w) >> 21 };
        #pragma unroll
        for (int j = 0; j < 4; j++) {
            unsigned int mask = __match_any_sync(0xffffffffu, ks[j]);
            int leader = __ffs(mask) - 1;
            if (lane == leader) atomicAdd(&sh[ks[j]], (unsigned int)__popc(mask));
        }
    }
    __syncthreads();
    for (int i = threadIdx.x; i < BINS; i += blockDim.x)
        if (sh[i]) atomicAdd(&g_hist2[b][i], sh[i]);
}

__global__ void fb_cut_kernel() {
    if (g_flag == 0) return;
    __shared__ unsigned int sb[BINS];
    __shared__ unsigned int csum[256];
    const int b = blockIdx.x;
    const int t = threadIdx.x;   // 256 threads

    #pragma unroll
    for (int i = 0; i < 8; i++) sb[t + i * 256] = g_hist2[b][t + i * 256];
    __syncthreads();
    unsigned int s = 0;
    #pragma unroll
    for (int i = 0; i < 8; i++) s += sb[t * 8 + i];
    csum[t] = s;
    __syncthreads();
    if (t == 0) {
        unsigned int acc = 0;
        int cut = 0;
        for (int c = 255; c >= 0; c--) {
            unsigned int ns = acc + csum[c];
            if (ns >= KTOP) {
                for (int i = 7; i >= 0; i--) {
                    acc += sb[c * 8 + i];
                    if (acc >= KTOP) { cut = c * 8 + i; break; }
                }
                break;
            }
            acc = ns;
        }
        g_thresh[b] = key2f((unsigned int)cut << 21);
    }
}

// ---------------------------------------------------------------------------
// Select: exact rank (key desc, index asc = jax top_k), gather boxes.
__global__ void select_kernel(const float* __restrict__ loc,
                              float* __restrict__ out) {
    __shared__ uint2 cand[CAP];
    const int b = blockIdx.x;
    const int n = min(g_cnt[b], CAP);
    for (int i = threadIdx.x; i < n; i += blockDim.x) cand[i] = g_cand[b][i];
    __syncthreads();

    for (int i = threadIdx.x; i < n; i += blockDim.x) {
        const unsigned int ki = u2key(cand[i].x);
        const unsigned int xi = cand[i].y;
        int rank = 0;
        for (int j = 0; j < n; j++) {
            unsigned int kj = u2key(cand[j].x);
            unsigned int xj = cand[j].y;
            rank += (kj > ki) || (kj == ki && xj < xi);
        }
        if (rank < KTOP) {
            unsigned int cls_id = xi % NCLS;
            unsigned int sp = xi / NCLS;
            float4 box = ((const float4*)(loc + (size_t)b * HW * 4))[sp];
            float* o = out + ((size_t)b * KTOP + rank) * 6;
            o[0] = box.x; o[1] = box.y; o[2] = box.z; o[3] = box.w;
            o[4] = key2f(ki);
            o[5] = (float)cls_id;
        }
    }
}

// ---------------------------------------------------------------------------
extern "C" void kernel_launch(void* const* d_in, const int* in_sizes, int n_in,
                              void* d_out, int out_size) {
    const float* cls = (const float*)d_in[0];
    const float* loc = (const float*)d_in[1];
    if (n_in >= 2 && in_sizes[0] < in_sizes[1]) {
        cls = (const float*)d_in[1];
        loc = (const float*)d_in[0];
    }
    float* out = (float*)d_out;

    init_kernel<<<1, 64>>>();
    sample_cut_kernel<<<BATCH, 1024>>>(cls);
    collect_kernel<<<dim3(256, BATCH), 256>>>(cls, 0);
    check_kernel<<<1, 1024>>>();
    // predicated exact fallback (no-ops when sampled path succeeded)
    fb_hist_kernel<<<dim3(128, BATCH), 256>>>(cls);
    fb_cut_kernel<<<BATCH, 256>>>();
    collect_kernel<<<dim3(256, BATCH), 256>>>(cls, 1);
    select_kernel<<<BATCH, 1024>>>(loc, out);
}